// round 5
// baseline (speedup 1.0000x reference)
#include <cuda_runtime.h>
#include <cfloat>

// Problem constants (from reference)
#define PB 7      // pooled bins per dim
#define HH 50
#define WW 50
#define CC 512
#define BB 2
#define RR 64
#define C4 (CC / 4)   // 128 float4 per pixel
#define BINS_PER_CTA 4

// One CTA = 4 consecutive output bins, 512 threads. Each 128-thread group
// owns one (b,r,py,px) bin; each thread owns one float4 channel slice.
// Per-thread code is identical to the R4 kernel (1 bin / thread, uniform
// switch dispatch) — only the CTA granularity changes, cutting CTA churn 4x.
//
// Facts proved from input ranges: extent in [7,26) => bin sizes sy,sx in
// [1,4]; window always fully in-bounds (max index y0+h-1 <= 48 < 50).

__device__ __forceinline__ void vmax(float4& m, float4 v) {
    m.x = fmaxf(m.x, v.x);
    m.y = fmaxf(m.y, v.y);
    m.z = fmaxf(m.z, v.z);
    m.w = fmaxf(m.w, v.w);
}

template<int SY, int SX>
__device__ __forceinline__ float4 binmax(const float4* __restrict__ p) {
    float4 v[SY * SX];
    #pragma unroll
    for (int dy = 0; dy < SY; ++dy)
        #pragma unroll
        for (int dx = 0; dx < SX; ++dx)
            v[dy * SX + dx] = __ldg(p + (dy * WW + dx) * C4);

    float4 m = v[0];
    #pragma unroll
    for (int k = 1; k < SY * SX; ++k)
        vmax(m, v[k]);
    return m;
}

__global__ __launch_bounds__(C4 * BINS_PER_CTA) void roipool_kernel(
    const float4* __restrict__ fm,    // (B,H,W,C) as float4
    const int*    __restrict__ rois,  // (B,R,4) int32: y0,x0,h,w
    float4*       __restrict__ out)   // (B,R,P,P,C) as float4
{
    int g  = threadIdx.x >> 7;            // bin group within CTA, 0..3
    int c4 = threadIdx.x & (C4 - 1);      // channel slice, 0..127

    int idx = blockIdx.x * BINS_PER_CTA + g;  // global bin id
    int px = idx % PB;
    int t  = idx / PB;
    int py = t % PB;
    t /= PB;
    int r = t % RR;
    int b = t / RR;

    const int4 roi = __ldg((const int4*)(rois + (b * RR + r) * 4));
    int y0 = roi.x, x0 = roi.y, h = roi.z, w = roi.w;

    // Bin bounds — fp32 arithmetic exactly as the reference:
    // step = extent/7 (fp32), start = trunc(i*step), end = trunc((i+1)*step),
    // last bin end = extent, size = max(end-start, 1).
    float stepy = (float)h / 7.0f;
    float stepx = (float)w / 7.0f;
    int ys = (int)((float)py * stepy);
    int ye = (py == PB - 1) ? h : (int)((float)(py + 1) * stepy);
    int sy = max(ye - ys, 1);
    int xs = (int)((float)px * stepx);
    int xe = (px == PB - 1) ? w : (int)((float)(px + 1) * stepx);
    int sx = max(xe - xs, 1);

    const float4* p = fm
        + ((size_t)((b * HH + (y0 + ys)) * WW + (x0 + xs))) * C4
        + c4;

    float4 m;
    int code = (sy - 1) * 4 + (sx - 1);   // uniform per warp: no divergence
    switch (code) {
        case  0: m = binmax<1,1>(p); break;
        case  1: m = binmax<1,2>(p); break;
        case  2: m = binmax<1,3>(p); break;
        case  3: m = binmax<1,4>(p); break;
        case  4: m = binmax<2,1>(p); break;
        case  5: m = binmax<2,2>(p); break;
        case  6: m = binmax<2,3>(p); break;
        case  7: m = binmax<2,4>(p); break;
        case  8: m = binmax<3,1>(p); break;
        case  9: m = binmax<3,2>(p); break;
        case 10: m = binmax<3,3>(p); break;
        case 11: m = binmax<3,4>(p); break;
        case 12: m = binmax<4,1>(p); break;
        case 13: m = binmax<4,2>(p); break;
        case 14: m = binmax<4,3>(p); break;
        default: m = binmax<4,4>(p); break;
    }

    out[(size_t)idx * C4 + c4] = m;
}

extern "C" void kernel_launch(void* const* d_in, const int* in_sizes, int n_in,
                              void* d_out, int out_size) {
    const float4* fm   = (const float4*)d_in[0];  // x_maps float32 (2,50,50,512)
    const int*    rois = (const int*)d_in[1];     // x_rois int32 (2,64,4)
    float4*       out  = (float4*)d_out;          // (2,64,7,7,512) float32

    int nblocks = (BB * RR * PB * PB) / BINS_PER_CTA;  // 1568
    roipool_kernel<<<nblocks, C4 * BINS_PER_CTA>>>(fm, rois, out);
}

// round 6
// speedup vs baseline: 1.1838x; 1.1838x over previous
#include <cuda_runtime.h>
#include <cfloat>

// Problem constants (from reference)
#define PB 7      // pooled bins per dim
#define HH 50
#define WW 50
#define CC 512
#define BB 2
#define RR 64
#define C4 (CC / 4)     // 128 float4 per pixel
#define NBINS (BB * RR * PB * PB)   // 6272
#define NCTA  (NBINS / 4)           // 1568: single wave, 4 bins per CTA
#define NRID  (BB * RR)             // 128 rois total

// Persistent single-wave kernel. CTA i handles bins {i, i+1568, i+3136, i+4704}.
// 1568 = 32*49, so all 4 bins share the same (py,px) — decoded once — and the
// roi id advances by 32 each iteration. Each thread owns one float4 channel
// slice; the (sy,sx) switch is warp-uniform (whole CTA shares one bin).
//
// Facts proved from input ranges: extent in [7,26) => bin sizes sy,sx in
// [1,4]; window always fully in-bounds (max index y0+h-1 <= 48 < 50).

__device__ __forceinline__ void vmax(float4& m, float4 v) {
    m.x = fmaxf(m.x, v.x);
    m.y = fmaxf(m.y, v.y);
    m.z = fmaxf(m.z, v.z);
    m.w = fmaxf(m.w, v.w);
}

template<int SY, int SX>
__device__ __forceinline__ float4 binmax(const float4* __restrict__ p) {
    float4 v[SY * SX];
    #pragma unroll
    for (int dy = 0; dy < SY; ++dy)
        #pragma unroll
        for (int dx = 0; dx < SX; ++dx)
            v[dy * SX + dx] = __ldg(p + (dy * WW + dx) * C4);

    float4 m = v[0];
    #pragma unroll
    for (int k = 1; k < SY * SX; ++k)
        vmax(m, v[k]);
    return m;
}

__global__ __launch_bounds__(C4) void roipool_kernel(
    const float4* __restrict__ fm,    // (B,H,W,C) as float4
    const int*    __restrict__ rois,  // (B,R,4) int32: y0,x0,h,w
    float4*       __restrict__ out)   // (B,R,P,P,C) as float4
{
    int binbase = blockIdx.x;         // 0..1567
    int px   = binbase % PB;
    int py   = (binbase / PB) % PB;
    int rid0 = binbase / (PB * PB);   // 0..31; iterations use rid0 + 32k

    int c4 = threadIdx.x;             // 0..127
    bool lasty = (py == PB - 1);
    bool lastx = (px == PB - 1);
    float fpy  = (float)py,      fpx  = (float)px;
    float fpy1 = (float)(py + 1), fpx1 = (float)(px + 1);

    // Prefetch first roi
    int4 roi = __ldg((const int4*)(rois + rid0 * 4));

    #pragma unroll
    for (int k = 0; k < 4; ++k) {
        int rid = rid0 + 32 * k;

        // Prefetch next iteration's roi before doing this bin's gather.
        int4 roi_n;
        if (k < 3)
            roi_n = __ldg((const int4*)(rois + (rid + 32) * 4));

        int y0 = roi.x, x0 = roi.y, h = roi.z, w = roi.w;

        // Bin bounds — fp32 arithmetic exactly as the reference:
        // step = extent/7, start = trunc(i*step), end = trunc((i+1)*step),
        // last bin end = extent, size = max(end-start, 1).
        float stepy = (float)h / 7.0f;
        float stepx = (float)w / 7.0f;
        int ys = (int)(fpy * stepy);
        int ye = lasty ? h : (int)(fpy1 * stepy);
        int sy = max(ye - ys, 1);
        int xs = (int)(fpx * stepx);
        int xe = lastx ? w : (int)(fpx1 * stepx);
        int sx = max(xe - xs, 1);

        // b = rid >> 6 folded into the fm offset: fm image stride = HH*WW px.
        const float4* p = fm
            + ((size_t)(((rid >> 6) * HH + (y0 + ys)) * WW + (x0 + xs))) * C4
            + c4;

        float4 m;
        int code = (sy - 1) * 4 + (sx - 1);   // uniform across CTA
        switch (code) {
            case  0: m = binmax<1,1>(p); break;
            case  1: m = binmax<1,2>(p); break;
            case  2: m = binmax<1,3>(p); break;
            case  3: m = binmax<1,4>(p); break;
            case  4: m = binmax<2,1>(p); break;
            case  5: m = binmax<2,2>(p); break;
            case  6: m = binmax<2,3>(p); break;
            case  7: m = binmax<2,4>(p); break;
            case  8: m = binmax<3,1>(p); break;
            case  9: m = binmax<3,2>(p); break;
            case 10: m = binmax<3,3>(p); break;
            case 11: m = binmax<3,4>(p); break;
            case 12: m = binmax<4,1>(p); break;
            case 13: m = binmax<4,2>(p); break;
            case 14: m = binmax<4,3>(p); break;
            default: m = binmax<4,4>(p); break;
        }

        // out bin index = rid*49 + py*7 + px
        out[(size_t)(rid * (PB * PB) + py * PB + px) * C4 + c4] = m;

        roi = roi_n;
    }
}

extern "C" void kernel_launch(void* const* d_in, const int* in_sizes, int n_in,
                              void* d_out, int out_size) {
    const float4* fm   = (const float4*)d_in[0];  // x_maps float32 (2,50,50,512)
    const int*    rois = (const int*)d_in[1];     // x_rois int32 (2,64,4)
    float4*       out  = (float4*)d_out;          // (2,64,7,7,512) float32

    roipool_kernel<<<NCTA, C4>>>(fm, rois, out);
}